// round 1
// baseline (speedup 1.0000x reference)
#include <cuda_runtime.h>
#include <cuda_bf16.h>
#include <math.h>

// Problem constants
#define Bdim 256
#define Gdim 2048
#define Fdim 128
#define Rdim 512
#define Kdim 128

// Scratch (device globals; no allocation allowed)
__device__ float g_scorer[Bdim * Fdim];
__device__ float g_norm[Bdim];
__device__ float g_scores[Bdim * Gdim];
__device__ int   g_topk_idx[Bdim * Kdim];
__device__ float g_tanhv[Bdim * Kdim];

// ---------------------------------------------------------------------------
// Kernel 1: scorer = tanh(h_t @ W_map + b_map); norm per row.
// 256 blocks x 128 threads. h_t row cached in smem; W reads coalesced.
// ---------------------------------------------------------------------------
__global__ void scorer_kernel(const float* __restrict__ h_t,
                              const float* __restrict__ W,
                              const float* __restrict__ bmap) {
    const int b = blockIdx.x;
    const int f = threadIdx.x;  // 0..127
    __shared__ float sh[Rdim];
    __shared__ float red[4];
    for (int r = f; r < Rdim; r += Fdim) sh[r] = h_t[b * Rdim + r];
    __syncthreads();

    float acc = bmap[f];
#pragma unroll 8
    for (int r = 0; r < Rdim; r++) acc = fmaf(sh[r], W[r * Fdim + f], acc);
    float sc = tanhf(acc);
    g_scorer[b * Fdim + f] = sc;

    // block reduce sum of squares (128 threads = 4 warps)
    float sq = sc * sc;
#pragma unroll
    for (int off = 16; off > 0; off >>= 1)
        sq += __shfl_down_sync(0xFFFFFFFFu, sq, off);
    if ((f & 31) == 0) red[f >> 5] = sq;
    __syncthreads();
    if (f == 0) {
        float s = red[0] + red[1] + red[2] + red[3];
        g_norm[b] = sqrtf(s);
    }
}

// ---------------------------------------------------------------------------
// Kernel 2: scores[b,g] = dot(node[b,g,:], scorer[b,:]) / norm[b] + mask[b,g]
// Grid (G/128, B), 256 threads (8 warps). Each warp: 16 rows, 2 at a time
// for MLP. float4 loads -> fully coalesced 512B/warp/row.
// ---------------------------------------------------------------------------
__global__ void scores_kernel(const float* __restrict__ node,
                              const float* __restrict__ mask) {
    const int b = blockIdx.y;
    const int g0 = blockIdx.x * 128;
    __shared__ float s_sc[Fdim];
    __shared__ float s_norm;

    if (threadIdx.x < Fdim) s_sc[threadIdx.x] = g_scorer[b * Fdim + threadIdx.x];
    if (threadIdx.x == 0) s_norm = g_norm[b];
    __syncthreads();

    const int warp = threadIdx.x >> 5;
    const int lane = threadIdx.x & 31;
    const float4 sc = reinterpret_cast<const float4*>(s_sc)[lane];
    const float norm = s_norm;
    const float4* nrow = reinterpret_cast<const float4*>(node) +
                         ((size_t)b * Gdim) * 32;

#pragma unroll
    for (int t = 0; t < 16; t += 2) {
        int r0 = g0 + warp * 16 + t;
        int r1 = r0 + 1;
        float4 a0 = nrow[(size_t)r0 * 32 + lane];
        float4 a1 = nrow[(size_t)r1 * 32 + lane];
        float d0 = a0.x * sc.x + a0.y * sc.y + a0.z * sc.z + a0.w * sc.w;
        float d1 = a1.x * sc.x + a1.y * sc.y + a1.z * sc.z + a1.w * sc.w;
#pragma unroll
        for (int off = 16; off > 0; off >>= 1) {
            d0 += __shfl_down_sync(0xFFFFFFFFu, d0, off);
            d1 += __shfl_down_sync(0xFFFFFFFFu, d1, off);
        }
        if (lane == 0) {
            g_scores[b * Gdim + r0] = d0 / norm + mask[b * Gdim + r0];
            g_scores[b * Gdim + r1] = d1 / norm + mask[b * Gdim + r1];
        }
    }
}

// ---------------------------------------------------------------------------
// Kernel 3: per batch row — full bitonic sort of 2048 (value,index) packed
// keys (descending value, ascending index on tie == jax.lax.top_k order),
// log-sum-exp, policy score, and top-128 index/tanh(value) extraction.
// 256 blocks x 1024 threads, 16KB smem keys.
// ---------------------------------------------------------------------------
__device__ __forceinline__ unsigned f2sortable(float v) {
    unsigned u = __float_as_uint(v);
    return (u & 0x80000000u) ? ~u : (u | 0x80000000u);
}
__device__ __forceinline__ float sortable2f(unsigned u) {
    return __uint_as_float((u & 0x80000000u) ? (u ^ 0x80000000u) : ~u);
}

__global__ void topk_kernel(float* __restrict__ out_policy) {
    const int b = blockIdx.x;
    const int tid = threadIdx.x;  // 1024
    __shared__ unsigned long long keys[Gdim];
    __shared__ float red[32];
    __shared__ float s_bcast;

    for (int i = tid; i < Gdim; i += 1024) {
        unsigned u = f2sortable(g_scores[b * Gdim + i]);
        keys[i] = ((unsigned long long)u << 32) | (unsigned)(0xFFFFFFFFu - (unsigned)i);
    }
    __syncthreads();

    // bitonic sort, overall DESCENDING
    for (int k = 2; k <= Gdim; k <<= 1) {
        for (int j = k >> 1; j > 0; j >>= 1) {
            for (int i = tid; i < Gdim; i += 1024) {
                int ixj = i ^ j;
                if (ixj > i) {
                    bool desc = ((i & k) == 0);
                    unsigned long long a = keys[i], c = keys[ixj];
                    bool sw = desc ? (a < c) : (a > c);
                    if (sw) { keys[i] = c; keys[ixj] = a; }
                }
            }
            __syncthreads();
        }
    }

    const float maxv = sortable2f((unsigned)(keys[0] >> 32));

    // sum of exp(x - max) over all 2048
    float s = 0.f;
    for (int i = tid; i < Gdim; i += 1024)
        s += expf(sortable2f((unsigned)(keys[i] >> 32)) - maxv);
#pragma unroll
    for (int off = 16; off > 0; off >>= 1)
        s += __shfl_down_sync(0xFFFFFFFFu, s, off);
    if ((tid & 31) == 0) red[tid >> 5] = s;
    __syncthreads();
    if (tid == 0) {
        float tot = 0.f;
#pragma unroll
        for (int w = 0; w < 32; w++) tot += red[w];
        s_bcast = logf(tot);
    }
    __syncthreads();
    const float lse = s_bcast;

    // top-128 extraction + policy partial
    float p = 0.f;
    if (tid < Kdim) {
        unsigned long long kk = keys[tid];
        float v = sortable2f((unsigned)(kk >> 32));
        int idx = (int)(0xFFFFFFFFu - (unsigned)(kk & 0xFFFFFFFFu));
        g_topk_idx[b * Kdim + tid] = idx;
        g_tanhv[b * Kdim + tid] = tanhf(v);
        p = (v - maxv) - lse;
    }
    __syncthreads();  // reuse red[]
    // reduce p over first 128 threads (4 warps)
#pragma unroll
    for (int off = 16; off > 0; off >>= 1)
        p += __shfl_down_sync(0xFFFFFFFFu, p, off);
    if (tid < Kdim && (tid & 31) == 0) red[tid >> 5] = p;
    __syncthreads();
    if (tid == 0)
        out_policy[b] = (red[0] + red[1] + red[2] + red[3]) * (1.0f / Kdim);
}

// ---------------------------------------------------------------------------
// Kernel 4: out[b, f, k] = node[b, idx[b,k], f] * tanhv[b,k]
// Grid (F/32, B), 256 threads. 128x33 smem tile: coalesced gather reads
// (along f) and coalesced transposed writes (along k), conflict-free.
// ---------------------------------------------------------------------------
__global__ void gather_kernel(const float* __restrict__ node,
                              float* __restrict__ out) {
    const int b = blockIdx.y;
    const int f0 = blockIdx.x * 32;
    __shared__ float tile[Kdim][33];
    const int tx = threadIdx.x & 31;
    const int ty = threadIdx.x >> 5;  // 0..7

    for (int kk = ty; kk < Kdim; kk += 8) {
        int idx = g_topk_idx[b * Kdim + kk];
        float t = g_tanhv[b * Kdim + kk];
        tile[kk][tx] = node[((size_t)b * Gdim + idx) * Fdim + f0 + tx] * t;
    }
    __syncthreads();

    for (int e = threadIdx.x; e < 32 * Kdim; e += 256) {
        int ff = e >> 7;       // 0..31
        int kk = e & 127;      // 0..127
        out[((size_t)b * Fdim + f0 + ff) * Kdim + kk] = tile[kk][ff];
    }
}

// ---------------------------------------------------------------------------
extern "C" void kernel_launch(void* const* d_in, const int* in_sizes, int n_in,
                              void* d_out, int out_size) {
    const float* node  = (const float*)d_in[0];  // [B, G, F]
    const float* mask  = (const float*)d_in[1];  // [B, G]
    const float* h_t   = (const float*)d_in[2];  // [B, RNN_DIM]
    const float* W_map = (const float*)d_in[3];  // [RNN_DIM, F]
    const float* b_map = (const float*)d_in[4];  // [F]

    float* out = (float*)d_out;                       // [B, F, K] then [B]
    float* out_policy = out + (size_t)Bdim * Fdim * Kdim;

    scorer_kernel<<<Bdim, Fdim>>>(h_t, W_map, b_map);
    {
        dim3 grid(Gdim / 128, Bdim);
        scores_kernel<<<grid, 256>>>(node, mask);
    }
    topk_kernel<<<Bdim, 1024>>>(out_policy);
    {
        dim3 grid(Fdim / 32, Bdim);
        gather_kernel<<<grid, 256>>>(node, out);
    }
}

// round 2
// speedup vs baseline: 1.0161x; 1.0161x over previous
#include <cuda_runtime.h>
#include <cuda_bf16.h>
#include <math.h>

#define Bdim 256
#define Gdim 2048
#define Fdim 128
#define Rdim 512
#define Kdim 128

__device__ float g_scorer[Bdim * Fdim];
__device__ float g_norm[Bdim];
__device__ float g_scores[Bdim * Gdim];
__device__ int   g_topk_idx[Bdim * Kdim];
__device__ float g_tanhv[Bdim * Kdim];

// ---------------------------------------------------------------------------
// Kernel 1: scorer = tanh(h_t @ W_map + b_map) and per-row norm.
// 64 blocks x 128 threads, 4 batch rows per block -> W read only 16x total.
// ---------------------------------------------------------------------------
#define BPB 4
__global__ void scorer_kernel(const float* __restrict__ h_t,
                              const float* __restrict__ W,
                              const float* __restrict__ bmap) {
    const int b0 = blockIdx.x * BPB;
    const int f = threadIdx.x;  // 0..127
    __shared__ float sh[BPB][Rdim];
    __shared__ float buf[BPB][Fdim];

    for (int i = f; i < BPB * Rdim; i += Fdim)
        ((float*)sh)[i] = h_t[b0 * Rdim + i];
    __syncthreads();

    float acc[BPB];
#pragma unroll
    for (int bb = 0; bb < BPB; bb++) acc[bb] = bmap[f];

#pragma unroll 8
    for (int r = 0; r < Rdim; r++) {
        float w = W[r * Fdim + f];
#pragma unroll
        for (int bb = 0; bb < BPB; bb++) acc[bb] = fmaf(sh[bb][r], w, acc[bb]);
    }
#pragma unroll
    for (int bb = 0; bb < BPB; bb++) {
        float sc = tanhf(acc[bb]);
        g_scorer[(b0 + bb) * Fdim + f] = sc;
        buf[bb][f] = sc * sc;
    }
    __syncthreads();

    // warp w reduces buf[w] (BPB == 4 warps)
    const int w = f >> 5, lane = f & 31;
    float s = buf[w][lane] + buf[w][lane + 32] + buf[w][lane + 64] + buf[w][lane + 96];
#pragma unroll
    for (int off = 16; off > 0; off >>= 1) s += __shfl_xor_sync(0xFFFFFFFFu, s, off);
    if (lane == 0) g_norm[b0 + w] = sqrtf(s);
}

// ---------------------------------------------------------------------------
// Kernel 2: scores[b,g] = dot(node[b,g,:], scorer[b,:]) / norm[b] + mask[b,g]
// Grid (16, 256), 256 threads. Each warp: 16 rows, 4 at a time (MLP=4).
// Butterfly reduce (all lanes hold sums) -> lane 0 writes float4 of scores.
// ---------------------------------------------------------------------------
__global__ void scores_kernel(const float* __restrict__ node,
                              const float* __restrict__ mask) {
    const int b = blockIdx.y;
    const int g0 = blockIdx.x * 128;
    __shared__ float s_sc[Fdim];
    __shared__ float s_norm;

    if (threadIdx.x < Fdim) s_sc[threadIdx.x] = g_scorer[b * Fdim + threadIdx.x];
    if (threadIdx.x == 0) s_norm = g_norm[b];
    __syncthreads();

    const int warp = threadIdx.x >> 5;
    const int lane = threadIdx.x & 31;
    const float4 sc = reinterpret_cast<const float4*>(s_sc)[lane];
    const float inv = 1.0f / s_norm;
    const float4* nrow = reinterpret_cast<const float4*>(node) + ((size_t)b * Gdim) * 32;
    const float4* mask4 = reinterpret_cast<const float4*>(mask + (size_t)b * Gdim);
    float4* out4 = reinterpret_cast<float4*>(g_scores + b * Gdim);

#pragma unroll
    for (int t = 0; t < 4; t++) {
        int r0 = g0 + warp * 16 + t * 4;
        float4 a0 = nrow[(size_t)(r0 + 0) * 32 + lane];
        float4 a1 = nrow[(size_t)(r0 + 1) * 32 + lane];
        float4 a2 = nrow[(size_t)(r0 + 2) * 32 + lane];
        float4 a3 = nrow[(size_t)(r0 + 3) * 32 + lane];
        float d0 = a0.x * sc.x + a0.y * sc.y + a0.z * sc.z + a0.w * sc.w;
        float d1 = a1.x * sc.x + a1.y * sc.y + a1.z * sc.z + a1.w * sc.w;
        float d2 = a2.x * sc.x + a2.y * sc.y + a2.z * sc.z + a2.w * sc.w;
        float d3 = a3.x * sc.x + a3.y * sc.y + a3.z * sc.z + a3.w * sc.w;
#pragma unroll
        for (int off = 16; off > 0; off >>= 1) {
            d0 += __shfl_xor_sync(0xFFFFFFFFu, d0, off);
            d1 += __shfl_xor_sync(0xFFFFFFFFu, d1, off);
            d2 += __shfl_xor_sync(0xFFFFFFFFu, d2, off);
            d3 += __shfl_xor_sync(0xFFFFFFFFu, d3, off);
        }
        if (lane == 0) {
            float4 m = mask4[r0 >> 2];
            float4 o;
            o.x = d0 * inv + m.x;
            o.y = d1 * inv + m.y;
            o.z = d2 * inv + m.z;
            o.w = d3 * inv + m.w;
            out4[r0 >> 2] = o;
        }
    }
}

// ---------------------------------------------------------------------------
// Kernel 3: per batch row — bitonic sort of 2048 packed (value,idx) keys,
// 2 keys/thread in REGISTERS. Stages j<=32 via shfl (no barriers), j=1
// in-thread, only j>=64 via smem (15 stages, 30 barriers vs 132 before).
// Then LSE + policy + top-128 extraction.
// ---------------------------------------------------------------------------
__device__ __forceinline__ unsigned f2sortable(float v) {
    unsigned u = __float_as_uint(v);
    return (u & 0x80000000u) ? ~u : (u | 0x80000000u);
}
__device__ __forceinline__ float sortable2f(unsigned u) {
    return __uint_as_float((u & 0x80000000u) ? (u ^ 0x80000000u) : ~u);
}
__device__ __forceinline__ unsigned long long umax64(unsigned long long a, unsigned long long b) { return a > b ? a : b; }
__device__ __forceinline__ unsigned long long umin64(unsigned long long a, unsigned long long b) { return a < b ? a : b; }

__global__ void __launch_bounds__(1024, 2) topk_kernel(float* __restrict__ out_policy) {
    const int b = blockIdx.x;
    const int t = threadIdx.x;  // 0..1023, owns elements 2t and 2t+1
    __shared__ unsigned long long s[Gdim];
    __shared__ float red[32];
    __shared__ float s_max, s_lse;

    // load + pack: descending value, ascending index on tie
    unsigned long long k0, k1;
    {
        float v0 = g_scores[b * Gdim + 2 * t];
        float v1 = g_scores[b * Gdim + 2 * t + 1];
        k0 = ((unsigned long long)f2sortable(v0) << 32) | (unsigned)(0xFFFFFFFFu - (unsigned)(2 * t));
        k1 = ((unsigned long long)f2sortable(v1) << 32) | (unsigned)(0xFFFFFFFFu - (unsigned)(2 * t + 1));
    }

#pragma unroll
    for (int kk = 2; kk <= Gdim; kk <<= 1) {
        // smem stages: j >= 64
#pragma unroll
        for (int j = kk >> 1; j >= 64; j >>= 1) {
            s[2 * t] = k0;
            s[2 * t + 1] = k1;
            __syncthreads();
            bool descT = (((2 * t) & kk) == 0);
            bool upper = (((2 * t) & j) != 0);
            unsigned long long o0 = s[(2 * t) ^ j];
            unsigned long long o1 = s[(2 * t + 1) ^ j];
            bool keepmax = (descT != upper);
            k0 = keepmax ? umax64(k0, o0) : umin64(k0, o0);
            k1 = keepmax ? umax64(k1, o1) : umin64(k1, o1);
            __syncthreads();
        }
        // shuffle stages: 2 <= j <= 32 (partner lane = lane ^ (j>>1))
#pragma unroll
        for (int j = (kk >> 1) < 32 ? (kk >> 1) : 32; j >= 2; j >>= 1) {
            unsigned long long o0 = __shfl_xor_sync(0xFFFFFFFFu, k0, j >> 1);
            unsigned long long o1 = __shfl_xor_sync(0xFFFFFFFFu, k1, j >> 1);
            bool descT = (((2 * t) & kk) == 0);
            bool upper = ((t & (j >> 1)) != 0);
            bool keepmax = (descT != upper);
            k0 = keepmax ? umax64(k0, o0) : umin64(k0, o0);
            k1 = keepmax ? umax64(k1, o1) : umin64(k1, o1);
        }
        // in-thread stage: j == 1
        {
            bool descT = (((2 * t) & kk) == 0);
            unsigned long long hi = umax64(k0, k1), lo = umin64(k0, k1);
            k0 = descT ? hi : lo;
            k1 = descT ? lo : hi;
        }
    }

    const float v0 = sortable2f((unsigned)(k0 >> 32));
    const float v1 = sortable2f((unsigned)(k1 >> 32));

    if (t == 0) s_max = v0;  // global max (element 0)
    __syncthreads();
    const float maxv = s_max;

    // log-sum-exp over all 2048
    float su = expf(v0 - maxv) + expf(v1 - maxv);
#pragma unroll
    for (int off = 16; off > 0; off >>= 1) su += __shfl_xor_sync(0xFFFFFFFFu, su, off);
    if ((t & 31) == 0) red[t >> 5] = su;
    __syncthreads();
    if (t == 0) {
        float tot = 0.f;
#pragma unroll
        for (int w = 0; w < 32; w++) tot += red[w];
        s_lse = logf(tot);
    }
    __syncthreads();
    const float lse = s_lse;

    // top-128: threads 0..63 hold sorted elems 2t, 2t+1
    float p = 0.f;
    if (t < 64) {
        int i0 = (int)(0xFFFFFFFFu - (unsigned)(k0 & 0xFFFFFFFFu));
        int i1 = (int)(0xFFFFFFFFu - (unsigned)(k1 & 0xFFFFFFFFu));
        g_topk_idx[b * Kdim + 2 * t]     = i0;
        g_topk_idx[b * Kdim + 2 * t + 1] = i1;
        g_tanhv[b * Kdim + 2 * t]     = tanhf(v0);
        g_tanhv[b * Kdim + 2 * t + 1] = tanhf(v1);
        p = (v0 - maxv - lse) + (v1 - maxv - lse);
    }
#pragma unroll
    for (int off = 16; off > 0; off >>= 1) p += __shfl_xor_sync(0xFFFFFFFFu, p, off);
    __syncthreads();
    if (t < 64 && (t & 31) == 0) red[t >> 5] = p;
    __syncthreads();
    if (t == 0) out_policy[b] = (red[0] + red[1]) * (1.0f / Kdim);
}

// ---------------------------------------------------------------------------
// Kernel 4: out[b,f,k] = node[b, idx[b,k], f] * tanhv[b,k]
// Grid (2, 256), 512 threads. idx/tanh staged in smem first (independent
// gather loads, MLP=8/thread). Tile 128k x 64f pitch-65 -> conflict-free
// transposed reads, fully coalesced writes.
// ---------------------------------------------------------------------------
__global__ void gather_kernel(const float* __restrict__ node,
                              float* __restrict__ out) {
    const int b = blockIdx.y;
    const int f0 = blockIdx.x * 64;
    __shared__ int   s_idx[Kdim];
    __shared__ float s_tv[Kdim];
    __shared__ float tile[Kdim][65];
    const int tid = threadIdx.x;  // 0..511

    if (tid < Kdim) {
        s_idx[tid] = g_topk_idx[b * Kdim + tid];
        s_tv[tid]  = g_tanhv[b * Kdim + tid];
    }
    __syncthreads();

    // load: 16 threads per row (16 float4 = 64 floats), 32 rows/iter, 4 iters
    const int f4 = tid & 15;
    const int r  = tid >> 4;  // 0..31
    const float4* node4 = reinterpret_cast<const float4*>(node);
#pragma unroll
    for (int it = 0; it < 4; it++) {
        int kk = r + it * 32;
        int idx = s_idx[kk];
        float tv = s_tv[kk];
        float4 v = node4[((size_t)b * Gdim + idx) * 32 + (f0 >> 2) + f4];
        tile[kk][f4 * 4 + 0] = v.x * tv;
        tile[kk][f4 * 4 + 1] = v.y * tv;
        tile[kk][f4 * 4 + 2] = v.z * tv;
        tile[kk][f4 * 4 + 3] = v.w * tv;
    }
    __syncthreads();

    // write: f = f0 + (tid>>7) + it*4, k = tid&127; coalesced along k
    const int kq = tid & 127;
    const int fq = tid >> 7;  // 0..3
#pragma unroll
    for (int it = 0; it < 16; it++) {
        int fl = fq + it * 4;           // 0..63 local f
        out[((size_t)b * Fdim + f0 + fl) * Kdim + kq] = tile[kq][fl];
    }
}

// ---------------------------------------------------------------------------
extern "C" void kernel_launch(void* const* d_in, const int* in_sizes, int n_in,
                              void* d_out, int out_size) {
    const float* node  = (const float*)d_in[0];
    const float* mask  = (const float*)d_in[1];
    const float* h_t   = (const float*)d_in[2];
    const float* W_map = (const float*)d_in[3];
    const float* b_map = (const float*)d_in[4];

    float* out = (float*)d_out;
    float* out_policy = out + (size_t)Bdim * Fdim * Kdim;

    scorer_kernel<<<Bdim / BPB, Fdim>>>(h_t, W_map, b_map);
    {
        dim3 grid(Gdim / 128, Bdim);
        scores_kernel<<<grid, 256>>>(node, mask);
    }
    topk_kernel<<<Bdim, 1024>>>(out_policy);
    {
        dim3 grid(2, Bdim);
        gather_kernel<<<grid, 512>>>(node, out);
    }
}

// round 3
// speedup vs baseline: 1.0287x; 1.0124x over previous
#include <cuda_runtime.h>
#include <cuda_bf16.h>
#include <math.h>

#define Bdim 256
#define Gdim 2048
#define Fdim 128
#define Rdim 512
#define Kdim 128

__device__ float g_scorer[Bdim * Fdim];
__device__ float g_norm[Bdim];
__device__ float g_scores[Bdim * Gdim];

__device__ __forceinline__ float tanh_fast(float x) {
    float y;
    asm("tanh.approx.f32 %0, %1;" : "=f"(y) : "f"(x));
    return y;
}

// ---------------------------------------------------------------------------
// Kernel 1: scorer = tanh(h_t @ W_map + b_map) and per-row norm.
// 64 blocks x 128 threads, 4 batch rows per block -> W read only 16x total.
// ---------------------------------------------------------------------------
#define BPB 4
__global__ void scorer_kernel(const float* __restrict__ h_t,
                              const float* __restrict__ W,
                              const float* __restrict__ bmap) {
    const int b0 = blockIdx.x * BPB;
    const int f = threadIdx.x;  // 0..127
    __shared__ float sh[BPB][Rdim];
    __shared__ float buf[BPB][Fdim];

    for (int i = f; i < BPB * Rdim; i += Fdim)
        ((float*)sh)[i] = h_t[b0 * Rdim + i];
    __syncthreads();

    float acc[BPB];
#pragma unroll
    for (int bb = 0; bb < BPB; bb++) acc[bb] = bmap[f];

#pragma unroll 8
    for (int r = 0; r < Rdim; r++) {
        float w = W[r * Fdim + f];
#pragma unroll
        for (int bb = 0; bb < BPB; bb++) acc[bb] = fmaf(sh[bb][r], w, acc[bb]);
    }
#pragma unroll
    for (int bb = 0; bb < BPB; bb++) {
        float sc = tanhf(acc[bb]);   // precise: feeds ordering
        g_scorer[(b0 + bb) * Fdim + f] = sc;
        buf[bb][f] = sc * sc;
    }
    __syncthreads();

    const int w = f >> 5, lane = f & 31;
    float s = buf[w][lane] + buf[w][lane + 32] + buf[w][lane + 64] + buf[w][lane + 96];
#pragma unroll
    for (int off = 16; off > 0; off >>= 1) s += __shfl_xor_sync(0xFFFFFFFFu, s, off);
    if (lane == 0) g_norm[b0 + w] = sqrtf(s);
}

// ---------------------------------------------------------------------------
// Kernel 2: scores[b,g] = dot(node[b,g,:], scorer[b,:]) / norm[b] + mask[b,g]
// Grid (16, 256) x 256 threads. Each warp: 16 rows, 8 at a time (MLP=8).
// ---------------------------------------------------------------------------
__global__ void scores_kernel(const float* __restrict__ node,
                              const float* __restrict__ mask) {
    const int b = blockIdx.y;
    const int g0 = blockIdx.x * 128;
    __shared__ float s_sc[Fdim];
    __shared__ float s_norm;

    if (threadIdx.x < Fdim) s_sc[threadIdx.x] = g_scorer[b * Fdim + threadIdx.x];
    if (threadIdx.x == 0) s_norm = g_norm[b];
    __syncthreads();

    const int warp = threadIdx.x >> 5;
    const int lane = threadIdx.x & 31;
    const float4 sc = reinterpret_cast<const float4*>(s_sc)[lane];
    const float inv = 1.0f / s_norm;
    const float4* nrow = reinterpret_cast<const float4*>(node) + ((size_t)b * Gdim) * 32;
    const float4* mask4 = reinterpret_cast<const float4*>(mask + (size_t)b * Gdim);
    float4* out4 = reinterpret_cast<float4*>(g_scores + b * Gdim);

#pragma unroll
    for (int t = 0; t < 2; t++) {
        const int r0 = g0 + warp * 16 + t * 8;
        float4 a[8];
        float d[8];
#pragma unroll
        for (int i = 0; i < 8; i++) a[i] = nrow[(size_t)(r0 + i) * 32 + lane];
#pragma unroll
        for (int i = 0; i < 8; i++)
            d[i] = a[i].x * sc.x + a[i].y * sc.y + a[i].z * sc.z + a[i].w * sc.w;
#pragma unroll
        for (int off = 16; off > 0; off >>= 1) {
#pragma unroll
            for (int i = 0; i < 8; i++) d[i] += __shfl_xor_sync(0xFFFFFFFFu, d[i], off);
        }
        if (lane == 0) {
            float4 m0 = mask4[(r0 >> 2) + 0];
            float4 m1 = mask4[(r0 >> 2) + 1];
            float4 o0, o1;
            o0.x = d[0] * inv + m0.x; o0.y = d[1] * inv + m0.y;
            o0.z = d[2] * inv + m0.z; o0.w = d[3] * inv + m0.w;
            o1.x = d[4] * inv + m1.x; o1.y = d[5] * inv + m1.y;
            o1.z = d[6] * inv + m1.z; o1.w = d[7] * inv + m1.w;
            out4[(r0 >> 2) + 0] = o0;
            out4[(r0 >> 2) + 1] = o1;
        }
    }
}

// ---------------------------------------------------------------------------
// Kernel 3 (fused): per batch row — bitonic sort of 2048 packed (value,idx)
// keys (2/thread in registers; j<=32 via shfl, j>=64 via smem), log-sum-exp,
// policy score, then in-place gather+transpose of the top-128 rows.
// Sort smem is reunioned as the transpose tile.
// ---------------------------------------------------------------------------
__device__ __forceinline__ unsigned f2sortable(float v) {
    unsigned u = __float_as_uint(v);
    return (u & 0x80000000u) ? ~u : (u | 0x80000000u);
}
__device__ __forceinline__ float sortable2f(unsigned u) {
    return __uint_as_float((u & 0x80000000u) ? (u ^ 0x80000000u) : ~u);
}
__device__ __forceinline__ unsigned long long umax64(unsigned long long a, unsigned long long b) { return a > b ? a : b; }
__device__ __forceinline__ unsigned long long umin64(unsigned long long a, unsigned long long b) { return a < b ? a : b; }

__global__ void __launch_bounds__(1024, 2)
topk_gather_kernel(const float* __restrict__ node,
                   float* __restrict__ out,
                   float* __restrict__ out_policy) {
    const int b = blockIdx.x;
    const int t = threadIdx.x;  // 0..1023, owns sorted elems 2t, 2t+1
    __shared__ union {
        unsigned long long keys[Gdim];        // 16 KB (sort phase)
        float tile[Kdim][33];                 // 16.9 KB (gather phase)
    } u;
    __shared__ int   s_idx[Kdim];
    __shared__ float s_tv[Kdim];
    __shared__ float red[32];
    __shared__ float s_max, s_lse;

    unsigned long long k0, k1;
    {
        float v0 = g_scores[b * Gdim + 2 * t];
        float v1 = g_scores[b * Gdim + 2 * t + 1];
        k0 = ((unsigned long long)f2sortable(v0) << 32) | (unsigned)(0xFFFFFFFFu - (unsigned)(2 * t));
        k1 = ((unsigned long long)f2sortable(v1) << 32) | (unsigned)(0xFFFFFFFFu - (unsigned)(2 * t + 1));
    }

#pragma unroll
    for (int kk = 2; kk <= Gdim; kk <<= 1) {
#pragma unroll
        for (int j = kk >> 1; j >= 64; j >>= 1) {
            u.keys[2 * t] = k0;
            u.keys[2 * t + 1] = k1;
            __syncthreads();
            bool descT = (((2 * t) & kk) == 0);
            bool upper = (((2 * t) & j) != 0);
            unsigned long long o0 = u.keys[(2 * t) ^ j];
            unsigned long long o1 = u.keys[(2 * t + 1) ^ j];
            bool keepmax = (descT != upper);
            k0 = keepmax ? umax64(k0, o0) : umin64(k0, o0);
            k1 = keepmax ? umax64(k1, o1) : umin64(k1, o1);
            __syncthreads();
        }
#pragma unroll
        for (int j = (kk >> 1) < 32 ? (kk >> 1) : 32; j >= 2; j >>= 1) {
            unsigned long long o0 = __shfl_xor_sync(0xFFFFFFFFu, k0, j >> 1);
            unsigned long long o1 = __shfl_xor_sync(0xFFFFFFFFu, k1, j >> 1);
            bool descT = (((2 * t) & kk) == 0);
            bool upper = ((t & (j >> 1)) != 0);
            bool keepmax = (descT != upper);
            k0 = keepmax ? umax64(k0, o0) : umin64(k0, o0);
            k1 = keepmax ? umax64(k1, o1) : umin64(k1, o1);
        }
        {
            bool descT = (((2 * t) & kk) == 0);
            unsigned long long hi = umax64(k0, k1), lo = umin64(k0, k1);
            k0 = descT ? hi : lo;
            k1 = descT ? lo : hi;
        }
    }

    const float v0 = sortable2f((unsigned)(k0 >> 32));
    const float v1 = sortable2f((unsigned)(k1 >> 32));

    if (t == 0) s_max = v0;
    __syncthreads();
    const float maxv = s_max;

    // log-sum-exp over all 2048 (fast math: feeds only policy score)
    float su = __expf(v0 - maxv) + __expf(v1 - maxv);
#pragma unroll
    for (int off = 16; off > 0; off >>= 1) su += __shfl_xor_sync(0xFFFFFFFFu, su, off);
    if ((t & 31) == 0) red[t >> 5] = su;
    __syncthreads();
    if (t == 0) {
        float tot = 0.f;
#pragma unroll
        for (int w = 0; w < 32; w++) tot += red[w];
        s_lse = __logf(tot);
    }
    __syncthreads();
    const float lse = s_lse;

    // top-128 indices + tanh(value), policy partial (threads 0..63)
    float p = 0.f;
    if (t < 64) {
        s_idx[2 * t]     = (int)(0xFFFFFFFFu - (unsigned)(k0 & 0xFFFFFFFFu));
        s_idx[2 * t + 1] = (int)(0xFFFFFFFFu - (unsigned)(k1 & 0xFFFFFFFFu));
        s_tv[2 * t]     = tanh_fast(v0);   // |tanh|~1 on top-k: rel err tiny
        s_tv[2 * t + 1] = tanh_fast(v1);
        p = (v0 - maxv - lse) + (v1 - maxv - lse);
    }
#pragma unroll
    for (int off = 16; off > 0; off >>= 1) p += __shfl_xor_sync(0xFFFFFFFFu, p, off);
    if (t == 0) red[0] = p;
    if (t == 32) red[1] = p;
    __syncthreads();
    if (t == 0) out_policy[b] = (red[0] + red[1]) * (1.0f / Kdim);

    // ---- gather + transpose: out[b,f,k] = node[b, idx[k], f] * tv[k] ----
    // keys smem is dead -> reuse as tile. Loads hoisted (MLP=4).
    const int row = t >> 3;        // 0..127 : k index
    const int f4  = t & 7;         // 0..7   : float4 within 32-f stage
    const int idx = s_idx[row];    // valid: s_idx written + synced above
    const float tv = s_tv[row];
    const float4* node4 = reinterpret_cast<const float4*>(node) +
                          ((size_t)b * Gdim + idx) * 32;
    float4 v[4];
#pragma unroll
    for (int s4 = 0; s4 < 4; s4++) v[s4] = node4[s4 * 8 + f4];

    const int kq = t & 127;        // writer: k index
    const int fq = t >> 7;         // writer: 0..7
#pragma unroll
    for (int s4 = 0; s4 < 4; s4++) {
        __syncthreads();           // tile free (keys dead / prev stage read)
        u.tile[row][f4 * 4 + 0] = v[s4].x * tv;
        u.tile[row][f4 * 4 + 1] = v[s4].y * tv;
        u.tile[row][f4 * 4 + 2] = v[s4].z * tv;
        u.tile[row][f4 * 4 + 3] = v[s4].w * tv;
        __syncthreads();
#pragma unroll
        for (int i = 0; i < 4; i++) {
            int fl = fq + i * 8;   // 0..31 local f
            out[((size_t)b * Fdim + s4 * 32 + fl) * Kdim + kq] = u.tile[kq][fl];
        }
    }
}

// ---------------------------------------------------------------------------
extern "C" void kernel_launch(void* const* d_in, const int* in_sizes, int n_in,
                              void* d_out, int out_size) {
    const float* node  = (const float*)d_in[0];
    const float* mask  = (const float*)d_in[1];
    const float* h_t   = (const float*)d_in[2];
    const float* W_map = (const float*)d_in[3];
    const float* b_map = (const float*)d_in[4];

    float* out = (float*)d_out;
    float* out_policy = out + (size_t)Bdim * Fdim * Kdim;

    scorer_kernel<<<Bdim / BPB, Fdim>>>(h_t, W_map, b_map);
    {
        dim3 grid(Gdim / 128, Bdim);
        scores_kernel<<<grid, 256>>>(node, mask);
    }
    topk_gather_kernel<<<Bdim, 1024>>>(node, out, out_policy);
}

// round 4
// speedup vs baseline: 1.6021x; 1.5574x over previous
#include <cuda_runtime.h>
#include <cuda_bf16.h>
#include <math.h>

#define Bdim 256
#define Gdim 2048
#define Fdim 128
#define Rdim 512
#define Kdim 128

__device__ float g_scorer[Bdim * Fdim];
__device__ float g_norm[Bdim];
__device__ float g_scores[Bdim * Gdim];

__device__ __forceinline__ float tanh_fast(float x) {
    float y;
    asm("tanh.approx.f32 %0, %1;" : "=f"(y) : "f"(x));
    return y;
}

// ---------------------------------------------------------------------------
// Kernel 1: scorer = tanh(h_t @ W_map + b_map) and per-row norm.
// 256 blocks (one per batch row) x 512 threads: thread (f, rc) computes the
// partial dot over r in [rc*128, (rc+1)*128). Full-chip occupancy; W read
// once per block (64 MB L2 traffic ~ 6 us at LTS cap).
// ---------------------------------------------------------------------------
__global__ void __launch_bounds__(512)
scorer_kernel(const float* __restrict__ h_t,
              const float* __restrict__ W,
              const float* __restrict__ bmap) {
    const int b = blockIdx.x;
    const int f = threadIdx.x & 127;
    const int rc = threadIdx.x >> 7;  // 0..3
    __shared__ float sh[Rdim];
    __shared__ float partial[4][Fdim];
    __shared__ float red[4];

    if (threadIdx.x < Rdim) sh[threadIdx.x] = h_t[b * Rdim + threadIdx.x];
    __syncthreads();

    float acc = 0.f;
    const float* Wp = W + (rc * 128) * Fdim + f;
    const float* hp = sh + rc * 128;
#pragma unroll 8
    for (int r = 0; r < 128; r++) acc = fmaf(hp[r], Wp[(size_t)r * Fdim], acc);
    partial[rc][f] = acc;
    __syncthreads();

    if (threadIdx.x < 128) {
        float sum = partial[0][f] + partial[1][f] + partial[2][f] + partial[3][f]
                  + bmap[f];
        float sc = tanhf(sum);   // precise: feeds ordering
        g_scorer[b * Fdim + f] = sc;
        float sq = sc * sc;
#pragma unroll
        for (int off = 16; off > 0; off >>= 1)
            sq += __shfl_xor_sync(0xFFFFFFFFu, sq, off);
        if ((f & 31) == 0) red[f >> 5] = sq;
    }
    __syncthreads();
    if (threadIdx.x == 0)
        g_norm[b] = sqrtf(red[0] + red[1] + red[2] + red[3]);
}

// ---------------------------------------------------------------------------
// Kernel 2: scores[b,g] = dot(node[b,g,:], scorer[b,:]) / norm[b] + mask[b,g]
// Grid (16, 256) x 256 threads. Each warp: 16 rows, 8 at a time (MLP=8).
// ---------------------------------------------------------------------------
__global__ void scores_kernel(const float* __restrict__ node,
                              const float* __restrict__ mask) {
    const int b = blockIdx.y;
    const int g0 = blockIdx.x * 128;
    __shared__ float s_sc[Fdim];
    __shared__ float s_norm;

    if (threadIdx.x < Fdim) s_sc[threadIdx.x] = g_scorer[b * Fdim + threadIdx.x];
    if (threadIdx.x == 0) s_norm = g_norm[b];
    __syncthreads();

    const int warp = threadIdx.x >> 5;
    const int lane = threadIdx.x & 31;
    const float4 sc = reinterpret_cast<const float4*>(s_sc)[lane];
    const float inv = 1.0f / s_norm;
    const float4* nrow = reinterpret_cast<const float4*>(node) + ((size_t)b * Gdim) * 32;
    const float4* mask4 = reinterpret_cast<const float4*>(mask + (size_t)b * Gdim);
    float4* out4 = reinterpret_cast<float4*>(g_scores + b * Gdim);

#pragma unroll
    for (int t = 0; t < 2; t++) {
        const int r0 = g0 + warp * 16 + t * 8;
        float4 a[8];
        float d[8];
#pragma unroll
        for (int i = 0; i < 8; i++) a[i] = nrow[(size_t)(r0 + i) * 32 + lane];
#pragma unroll
        for (int i = 0; i < 8; i++)
            d[i] = a[i].x * sc.x + a[i].y * sc.y + a[i].z * sc.z + a[i].w * sc.w;
#pragma unroll
        for (int off = 16; off > 0; off >>= 1) {
#pragma unroll
            for (int i = 0; i < 8; i++) d[i] += __shfl_xor_sync(0xFFFFFFFFu, d[i], off);
        }
        if (lane == 0) {
            float4 m0 = mask4[(r0 >> 2) + 0];
            float4 m1 = mask4[(r0 >> 2) + 1];
            float4 o0, o1;
            o0.x = d[0] * inv + m0.x; o0.y = d[1] * inv + m0.y;
            o0.z = d[2] * inv + m0.z; o0.w = d[3] * inv + m0.w;
            o1.x = d[4] * inv + m1.x; o1.y = d[5] * inv + m1.y;
            o1.z = d[6] * inv + m1.z; o1.w = d[7] * inv + m1.w;
            out4[(r0 >> 2) + 0] = o0;
            out4[(r0 >> 2) + 1] = o1;
        }
    }
}

// ---------------------------------------------------------------------------
// Kernel 3 (fused): per batch row — bitonic sort of 2048 packed (value,idx)
// keys (2/thread in registers; j<=32 via shfl, j>=64 via smem), log-sum-exp,
// policy score, then in-place gather+transpose of the top-128 rows.
// ---------------------------------------------------------------------------
__device__ __forceinline__ unsigned f2sortable(float v) {
    unsigned u = __float_as_uint(v);
    return (u & 0x80000000u) ? ~u : (u | 0x80000000u);
}
__device__ __forceinline__ float sortable2f(unsigned u) {
    return __uint_as_float((u & 0x80000000u) ? (u ^ 0x80000000u) : ~u);
}
__device__ __forceinline__ unsigned long long umax64(unsigned long long a, unsigned long long b) { return a > b ? a : b; }
__device__ __forceinline__ unsigned long long umin64(unsigned long long a, unsigned long long b) { return a < b ? a : b; }

__global__ void __launch_bounds__(1024, 2)
topk_gather_kernel(const float* __restrict__ node,
                   float* __restrict__ out,
                   float* __restrict__ out_policy) {
    const int b = blockIdx.x;
    const int t = threadIdx.x;  // 0..1023, owns sorted elems 2t, 2t+1
    __shared__ union {
        unsigned long long keys[Gdim];        // 16 KB (sort phase)
        float tile[Kdim][33];                 // 16.9 KB (gather phase)
    } u;
    __shared__ int   s_idx[Kdim];
    __shared__ float s_tv[Kdim];
    __shared__ float red[32];
    __shared__ float s_max, s_lse;

    unsigned long long k0, k1;
    {
        float v0 = g_scores[b * Gdim + 2 * t];
        float v1 = g_scores[b * Gdim + 2 * t + 1];
        k0 = ((unsigned long long)f2sortable(v0) << 32) | (unsigned)(0xFFFFFFFFu - (unsigned)(2 * t));
        k1 = ((unsigned long long)f2sortable(v1) << 32) | (unsigned)(0xFFFFFFFFu - (unsigned)(2 * t + 1));
    }

#pragma unroll
    for (int kk = 2; kk <= Gdim; kk <<= 1) {
#pragma unroll
        for (int j = kk >> 1; j >= 64; j >>= 1) {
            u.keys[2 * t] = k0;
            u.keys[2 * t + 1] = k1;
            __syncthreads();
            bool descT = (((2 * t) & kk) == 0);
            bool upper = (((2 * t) & j) != 0);
            unsigned long long o0 = u.keys[(2 * t) ^ j];
            unsigned long long o1 = u.keys[(2 * t + 1) ^ j];
            bool keepmax = (descT != upper);
            k0 = keepmax ? umax64(k0, o0) : umin64(k0, o0);
            k1 = keepmax ? umax64(k1, o1) : umin64(k1, o1);
            __syncthreads();
        }
#pragma unroll
        for (int j = (kk >> 1) < 32 ? (kk >> 1) : 32; j >= 2; j >>= 1) {
            unsigned long long o0 = __shfl_xor_sync(0xFFFFFFFFu, k0, j >> 1);
            unsigned long long o1 = __shfl_xor_sync(0xFFFFFFFFu, k1, j >> 1);
            bool descT = (((2 * t) & kk) == 0);
            bool upper = ((t & (j >> 1)) != 0);
            bool keepmax = (descT != upper);
            k0 = keepmax ? umax64(k0, o0) : umin64(k0, o0);
            k1 = keepmax ? umax64(k1, o1) : umin64(k1, o1);
        }
        {
            bool descT = (((2 * t) & kk) == 0);
            unsigned long long hi = umax64(k0, k1), lo = umin64(k0, k1);
            k0 = descT ? hi : lo;
            k1 = descT ? lo : hi;
        }
    }

    const float v0 = sortable2f((unsigned)(k0 >> 32));
    const float v1 = sortable2f((unsigned)(k1 >> 32));

    if (t == 0) s_max = v0;
    __syncthreads();
    const float maxv = s_max;

    float su = __expf(v0 - maxv) + __expf(v1 - maxv);
#pragma unroll
    for (int off = 16; off > 0; off >>= 1) su += __shfl_xor_sync(0xFFFFFFFFu, su, off);
    if ((t & 31) == 0) red[t >> 5] = su;
    __syncthreads();
    if (t == 0) {
        float tot = 0.f;
#pragma unroll
        for (int w = 0; w < 32; w++) tot += red[w];
        s_lse = __logf(tot);
    }
    __syncthreads();
    const float lse = s_lse;

    float p = 0.f;
    if (t < 64) {
        s_idx[2 * t]     = (int)(0xFFFFFFFFu - (unsigned)(k0 & 0xFFFFFFFFu));
        s_idx[2 * t + 1] = (int)(0xFFFFFFFFu - (unsigned)(k1 & 0xFFFFFFFFu));
        s_tv[2 * t]     = tanh_fast(v0);
        s_tv[2 * t + 1] = tanh_fast(v1);
        p = (v0 - maxv - lse) + (v1 - maxv - lse);
    }
#pragma unroll
    for (int off = 16; off > 0; off >>= 1) p += __shfl_xor_sync(0xFFFFFFFFu, p, off);
    if (t == 0) red[0] = p;
    if (t == 32) red[1] = p;
    __syncthreads();
    if (t == 0) out_policy[b] = (red[0] + red[1]) * (1.0f / Kdim);

    // ---- gather + transpose: out[b,f,k] = node[b, idx[k], f] * tv[k] ----
    const int row = t >> 3;        // 0..127 : k index
    const int f4  = t & 7;         // 0..7
    const int idx = s_idx[row];
    const float tv = s_tv[row];
    const float4* node4 = reinterpret_cast<const float4*>(node) +
                          ((size_t)b * Gdim + idx) * 32;
    float4 v[4];
#pragma unroll
    for (int s4 = 0; s4 < 4; s4++) v[s4] = node4[s4 * 8 + f4];

    const int kq = t & 127;
    const int fq = t >> 7;
#pragma unroll
    for (int s4 = 0; s4 < 4; s4++) {
        __syncthreads();
        u.tile[row][f4 * 4 + 0] = v[s4].x * tv;
        u.tile[row][f4 * 4 + 1] = v[s4].y * tv;
        u.tile[row][f4 * 4 + 2] = v[s4].z * tv;
        u.tile[row][f4 * 4 + 3] = v[s4].w * tv;
        __syncthreads();
#pragma unroll
        for (int i = 0; i < 4; i++) {
            int fl = fq + i * 8;
            out[((size_t)b * Fdim + s4 * 32 + fl) * Kdim + kq] = u.tile[kq][fl];
        }
    }
}

// ---------------------------------------------------------------------------
extern "C" void kernel_launch(void* const* d_in, const int* in_sizes, int n_in,
                              void* d_out, int out_size) {
    const float* node  = (const float*)d_in[0];
    const float* mask  = (const float*)d_in[1];
    const float* h_t   = (const float*)d_in[2];
    const float* W_map = (const float*)d_in[3];
    const float* b_map = (const float*)d_in[4];

    float* out = (float*)d_out;
    float* out_policy = out + (size_t)Bdim * Fdim * Kdim;

    scorer_kernel<<<Bdim, 512>>>(h_t, W_map, b_map);
    {
        dim3 grid(Gdim / 128, Bdim);
        scores_kernel<<<grid, 256>>>(node, mask);
    }
    topk_gather_kernel<<<Bdim, 1024>>>(node, out, out_policy);
}

// round 5
// speedup vs baseline: 1.6419x; 1.0249x over previous
#include <cuda_runtime.h>
#include <cuda_bf16.h>
#include <math.h>

#define Bdim 256
#define Gdim 2048
#define Fdim 128
#define Rdim 512
#define Kdim 128

__device__ float g_scorer[Bdim * Fdim];
__device__ float g_norm[Bdim];
__device__ float g_scores[Bdim * Gdim];

__device__ __forceinline__ float tanh_fast(float x) {
    float y;
    asm("tanh.approx.f32 %0, %1;" : "=f"(y) : "f"(x));
    return y;
}

// ---------------------------------------------------------------------------
// Kernel 1: scorer = tanh(h_t @ W_map + b_map) and per-row norm.
// 256 blocks x 512 threads. Thread (f4, rc): f4 = tid&31 owns 4 f-columns
// (float4), rc = tid>>5 owns 32 r's. 4 INDEPENDENT accumulator chains,
// 32 independent float4 loads (coalesced 512B/warp). Smem reduce over rc.
// ---------------------------------------------------------------------------
__global__ void __launch_bounds__(512)
scorer_kernel(const float* __restrict__ h_t,
              const float* __restrict__ W,
              const float* __restrict__ bmap) {
    const int b = blockIdx.x;
    const int f4 = threadIdx.x & 31;   // float4 column group: f = 4*f4..4*f4+3
    const int rc = threadIdx.x >> 5;   // 0..15, r chunk of 32
    __shared__ float sh[Rdim];
    __shared__ float4 partial[16][32];  // [rc][f4]
    __shared__ float red[4];

    if (threadIdx.x < Rdim) sh[threadIdx.x] = h_t[b * Rdim + threadIdx.x];
    __syncthreads();

    const float4* W4 = reinterpret_cast<const float4*>(W);  // [Rdim][32]
    float4 acc = make_float4(0.f, 0.f, 0.f, 0.f);
    const int rbase = rc * 32;
#pragma unroll
    for (int r = 0; r < 32; r++) {
        float h = sh[rbase + r];
        float4 w = W4[(size_t)(rbase + r) * 32 + f4];
        acc.x = fmaf(h, w.x, acc.x);
        acc.y = fmaf(h, w.y, acc.y);
        acc.z = fmaf(h, w.z, acc.z);
        acc.w = fmaf(h, w.w, acc.w);
    }
    partial[rc][f4] = acc;
    __syncthreads();

    // threads 0..127: f = tid, sum the 16 partials for this f
    if (threadIdx.x < Fdim) {
        const int f = threadIdx.x;
        const float* pc = reinterpret_cast<const float*>(partial);  // [16][128]
        float sum = bmap[f];
#pragma unroll
        for (int c = 0; c < 16; c++) sum += pc[c * 128 + f];
        float sc = tanhf(sum);   // precise: feeds ordering
        g_scorer[b * Fdim + f] = sc;
        float sq = sc * sc;
#pragma unroll
        for (int off = 16; off > 0; off >>= 1)
            sq += __shfl_xor_sync(0xFFFFFFFFu, sq, off);
        if ((f & 31) == 0) red[f >> 5] = sq;
    }
    __syncthreads();
    if (threadIdx.x == 0)
        g_norm[b] = sqrtf(red[0] + red[1] + red[2] + red[3]);
}

// ---------------------------------------------------------------------------
// Kernel 2: scores[b,g] = dot(node[b,g,:], scorer[b,:]) / norm[b] + mask[b,g]
// Grid (16, 256) x 256 threads. Each warp: 16 rows, ALL 16 loads issued
// up-front (MLP=16), then FMAs, then butterfly reduce, lane0 writes 4x f4.
// ---------------------------------------------------------------------------
__global__ void scores_kernel(const float* __restrict__ node,
                              const float* __restrict__ mask) {
    const int b = blockIdx.y;
    const int g0 = blockIdx.x * 128;
    __shared__ float s_sc[Fdim];
    __shared__ float s_norm;

    if (threadIdx.x < Fdim) s_sc[threadIdx.x] = g_scorer[b * Fdim + threadIdx.x];
    if (threadIdx.x == 0) s_norm = g_norm[b];
    __syncthreads();

    const int warp = threadIdx.x >> 5;
    const int lane = threadIdx.x & 31;
    const float4 sc = reinterpret_cast<const float4*>(s_sc)[lane];
    const float inv = 1.0f / s_norm;
    const float4* nrow = reinterpret_cast<const float4*>(node) + ((size_t)b * Gdim) * 32;
    const float4* mask4 = reinterpret_cast<const float4*>(mask + (size_t)b * Gdim);
    float4* out4 = reinterpret_cast<float4*>(g_scores + b * Gdim);

    const int r0 = g0 + warp * 16;
    float4 a[16];
    float d[16];
#pragma unroll
    for (int i = 0; i < 16; i++) a[i] = nrow[(size_t)(r0 + i) * 32 + lane];
#pragma unroll
    for (int i = 0; i < 16; i++)
        d[i] = a[i].x * sc.x + a[i].y * sc.y + a[i].z * sc.z + a[i].w * sc.w;
#pragma unroll
    for (int off = 16; off > 0; off >>= 1) {
#pragma unroll
        for (int i = 0; i < 16; i++) d[i] += __shfl_xor_sync(0xFFFFFFFFu, d[i], off);
    }
    if (lane == 0) {
#pragma unroll
        for (int q = 0; q < 4; q++) {
            float4 m = mask4[(r0 >> 2) + q];
            float4 o;
            o.x = d[q * 4 + 0] * inv + m.x;
            o.y = d[q * 4 + 1] * inv + m.y;
            o.z = d[q * 4 + 2] * inv + m.z;
            o.w = d[q * 4 + 3] * inv + m.w;
            out4[(r0 >> 2) + q] = o;
        }
    }
}

// ---------------------------------------------------------------------------
// Kernel 3 (fused): per batch row — bitonic sort of 2048 packed (value,idx)
// keys (2/thread in registers; j<=32 via shfl, j>=64 via smem), log-sum-exp,
// policy score, then in-place gather+transpose of the top-128 rows.
// ---------------------------------------------------------------------------
__device__ __forceinline__ unsigned f2sortable(float v) {
    unsigned u = __float_as_uint(v);
    return (u & 0x80000000u) ? ~u : (u | 0x80000000u);
}
__device__ __forceinline__ float sortable2f(unsigned u) {
    return __uint_as_float((u & 0x80000000u) ? (u ^ 0x80000000u) : ~u);
}
__device__ __forceinline__ unsigned long long umax64(unsigned long long a, unsigned long long b) { return a > b ? a : b; }
__device__ __forceinline__ unsigned long long umin64(unsigned long long a, unsigned long long b) { return a < b ? a : b; }

__global__ void __launch_bounds__(1024, 2)
topk_gather_kernel(const float* __restrict__ node,
                   float* __restrict__ out,
                   float* __restrict__ out_policy) {
    const int b = blockIdx.x;
    const int t = threadIdx.x;
    __shared__ union {
        unsigned long long keys[Gdim];
        float tile[Kdim][33];
    } u;
    __shared__ int   s_idx[Kdim];
    __shared__ float s_tv[Kdim];
    __shared__ float red[32];
    __shared__ float s_max, s_lse;

    unsigned long long k0, k1;
    {
        float v0 = g_scores[b * Gdim + 2 * t];
        float v1 = g_scores[b * Gdim + 2 * t + 1];
        k0 = ((unsigned long long)f2sortable(v0) << 32) | (unsigned)(0xFFFFFFFFu - (unsigned)(2 * t));
        k1 = ((unsigned long long)f2sortable(v1) << 32) | (unsigned)(0xFFFFFFFFu - (unsigned)(2 * t + 1));
    }

#pragma unroll
    for (int kk = 2; kk <= Gdim; kk <<= 1) {
#pragma unroll
        for (int j = kk >> 1; j >= 64; j >>= 1) {
            u.keys[2 * t] = k0;
            u.keys[2 * t + 1] = k1;
            __syncthreads();
            bool descT = (((2 * t) & kk) == 0);
            bool upper = (((2 * t) & j) != 0);
            unsigned long long o0 = u.keys[(2 * t) ^ j];
            unsigned long long o1 = u.keys[(2 * t + 1) ^ j];
            bool keepmax = (descT != upper);
            k0 = keepmax ? umax64(k0, o0) : umin64(k0, o0);
            k1 = keepmax ? umax64(k1, o1) : umin64(k1, o1);
            __syncthreads();
        }
#pragma unroll
        for (int j = (kk >> 1) < 32 ? (kk >> 1) : 32; j >= 2; j >>= 1) {
            unsigned long long o0 = __shfl_xor_sync(0xFFFFFFFFu, k0, j >> 1);
            unsigned long long o1 = __shfl_xor_sync(0xFFFFFFFFu, k1, j >> 1);
            bool descT = (((2 * t) & kk) == 0);
            bool upper = ((t & (j >> 1)) != 0);
            bool keepmax = (descT != upper);
            k0 = keepmax ? umax64(k0, o0) : umin64(k0, o0);
            k1 = keepmax ? umax64(k1, o1) : umin64(k1, o1);
        }
        {
            bool descT = (((2 * t) & kk) == 0);
            unsigned long long hi = umax64(k0, k1), lo = umin64(k0, k1);
            k0 = descT ? hi : lo;
            k1 = descT ? lo : hi;
        }
    }

    const float v0 = sortable2f((unsigned)(k0 >> 32));
    const float v1 = sortable2f((unsigned)(k1 >> 32));

    if (t == 0) s_max = v0;
    __syncthreads();
    const float maxv = s_max;

    float su = __expf(v0 - maxv) + __expf(v1 - maxv);
#pragma unroll
    for (int off = 16; off > 0; off >>= 1) su += __shfl_xor_sync(0xFFFFFFFFu, su, off);
    if ((t & 31) == 0) red[t >> 5] = su;
    __syncthreads();
    if (t == 0) {
        float tot = 0.f;
#pragma unroll
        for (int w = 0; w < 32; w++) tot += red[w];
        s_lse = __logf(tot);
    }
    __syncthreads();
    const float lse = s_lse;

    float p = 0.f;
    if (t < 64) {
        s_idx[2 * t]     = (int)(0xFFFFFFFFu - (unsigned)(k0 & 0xFFFFFFFFu));
        s_idx[2 * t + 1] = (int)(0xFFFFFFFFu - (unsigned)(k1 & 0xFFFFFFFFu));
        s_tv[2 * t]     = tanh_fast(v0);
        s_tv[2 * t + 1] = tanh_fast(v1);
        p = (v0 - maxv - lse) + (v1 - maxv - lse);
    }
#pragma unroll
    for (int off = 16; off > 0; off >>= 1) p += __shfl_xor_sync(0xFFFFFFFFu, p, off);
    if (t == 0) red[0] = p;
    if (t == 32) red[1] = p;
    __syncthreads();
    if (t == 0) out_policy[b] = (red[0] + red[1]) * (1.0f / Kdim);

    // ---- gather + transpose: out[b,f,k] = node[b, idx[k], f] * tv[k] ----
    const int row = t >> 3;
    const int f4  = t & 7;
    const int idx = s_idx[row];
    const float tv = s_tv[row];
    const float4* node4 = reinterpret_cast<const float4*>(node) +
                          ((size_t)b * Gdim + idx) * 32;
    float4 v[4];
#pragma unroll
    for (int s4 = 0; s4 < 4; s4++) v[s4] = node4[s4 * 8 + f4];

    const int kq = t & 127;
    const int fq = t >> 7;
#pragma unroll
    for (int s4 = 0; s4 < 4; s4++) {
        __syncthreads();
        u.tile[row][f4 * 4 + 0] = v[s4].x * tv;
        u.tile[row][f4 * 4 + 1] = v[s4].y * tv;
        u.tile[row][f4 * 4 + 2] = v[s4].z * tv;
        u.tile[row][f4 * 4 + 3] = v[s4].w * tv;
        __syncthreads();
#pragma unroll
        for (int i = 0; i < 4; i++) {
            int fl = fq + i * 8;
            out[((size_t)b * Fdim + s4 * 32 + fl) * Kdim + kq] = u.tile[kq][fl];
        }
    }
}

// ---------------------------------------------------------------------------
extern "C" void kernel_launch(void* const* d_in, const int* in_sizes, int n_in,
                              void* d_out, int out_size) {
    const float* node  = (const float*)d_in[0];
    const float* mask  = (const float*)d_in[1];
    const float* h_t   = (const float*)d_in[2];
    const float* W_map = (const float*)d_in[3];
    const float* b_map = (const float*)d_in[4];

    float* out = (float*)d_out;
    float* out_policy = out + (size_t)Bdim * Fdim * Kdim;

    scorer_kernel<<<Bdim, 512>>>(h_t, W_map, b_map);
    {
        dim3 grid(Gdim / 128, Bdim);
        scores_kernel<<<grid, 256>>>(node, mask);
    }
    topk_gather_kernel<<<Bdim, 1024>>>(node, out, out_policy);
}

// round 7
// speedup vs baseline: 1.8224x; 1.1099x over previous
#include <cuda_runtime.h>
#include <cuda_bf16.h>
#include <math.h>

#define Bdim 256
#define Gdim 2048
#define Fdim 128
#define Rdim 512
#define Kdim 128

__device__ float g_scorer[Bdim * Fdim];
__device__ float g_normsq[Bdim * 2];   // per (b, f-half) partial sum of squares
__device__ float g_scores[Bdim * Gdim];

__device__ __forceinline__ float tanh_fast(float x) {
    float y;
    asm("tanh.approx.f32 %0, %1;" : "=f"(y) : "f"(x));
    return y;
}

// ---------------------------------------------------------------------------
// Kernel 1: scorer = tanh(h_t @ W_map + b_map), partial norms.
// Grid (2, 256) x 256 threads: block (fc, b) computes f in [fc*64, fc*64+64).
// Thread (f4 = tid&15, rc = tid>>4): 4 f-columns (float4), 32 r's.
// ---------------------------------------------------------------------------
__global__ void __launch_bounds__(256)
scorer_kernel(const float* __restrict__ h_t,
              const float* __restrict__ W,
              const float* __restrict__ bmap) {
    const int fc = blockIdx.x;         // 0..1
    const int b  = blockIdx.y;
    const int f4 = threadIdx.x & 15;   // local float4 col (f_local = 4*f4..)
    const int rc = threadIdx.x >> 4;   // 0..15, r chunk of 32
    __shared__ float sh[Rdim];
    __shared__ float4 partial[16][16];  // [rc][f4]
    __shared__ float red[2];

    for (int i = threadIdx.x; i < Rdim; i += 256) sh[i] = h_t[b * Rdim + i];
    __syncthreads();

    const float4* W4 = reinterpret_cast<const float4*>(W);  // [Rdim][32]
    float4 acc = make_float4(0.f, 0.f, 0.f, 0.f);
    const int rbase = rc * 32;
    const int f4g = fc * 16 + f4;      // global float4 col
#pragma unroll
    for (int r = 0; r < 32; r++) {
        float h = sh[rbase + r];
        float4 w = W4[(size_t)(rbase + r) * 32 + f4g];
        acc.x = fmaf(h, w.x, acc.x);
        acc.y = fmaf(h, w.y, acc.y);
        acc.z = fmaf(h, w.z, acc.z);
        acc.w = fmaf(h, w.w, acc.w);
    }
    partial[rc][f4] = acc;
    __syncthreads();

    if (threadIdx.x < 64) {
        const int fl = threadIdx.x;            // local f
        const int f  = fc * 64 + fl;           // global f
        const float* pc = reinterpret_cast<const float*>(partial);  // [16][64]
        float sum = bmap[f];
#pragma unroll
        for (int c = 0; c < 16; c++) sum += pc[c * 64 + fl];
        float sc = tanhf(sum);   // precise: feeds ordering
        g_scorer[b * Fdim + f] = sc;
        float sq = sc * sc;
#pragma unroll
        for (int off = 16; off > 0; off >>= 1)
            sq += __shfl_xor_sync(0xFFFFFFFFu, sq, off);
        if ((fl & 31) == 0) red[fl >> 5] = sq;
    }
    __syncthreads();
    if (threadIdx.x == 0) g_normsq[b * 2 + fc] = red[0] + red[1];
}

// ---------------------------------------------------------------------------
// Kernel 2: scores[b,g] = dot(node[b,g,:], scorer[b,:]) / norm + mask[b,g]
// Grid (16, 256) x 256 threads. Warp: 16 rows, loads up-front, streaming.
// ---------------------------------------------------------------------------
__global__ void scores_kernel(const float* __restrict__ node,
                              const float* __restrict__ mask) {
    const int b = blockIdx.y;
    const int g0 = blockIdx.x * 128;
    __shared__ float s_sc[Fdim];
    __shared__ float s_inv;

    if (threadIdx.x < Fdim) s_sc[threadIdx.x] = g_scorer[b * Fdim + threadIdx.x];
    if (threadIdx.x == 0)
        s_inv = 1.0f / sqrtf(g_normsq[b * 2] + g_normsq[b * 2 + 1]);
    __syncthreads();

    const int warp = threadIdx.x >> 5;
    const int lane = threadIdx.x & 31;
    const float4 sc = reinterpret_cast<const float4*>(s_sc)[lane];
    const float inv = s_inv;
    const float4* nrow = reinterpret_cast<const float4*>(node) + ((size_t)b * Gdim) * 32;
    const float4* mask4 = reinterpret_cast<const float4*>(mask + (size_t)b * Gdim);
    float4* out4 = reinterpret_cast<float4*>(g_scores + b * Gdim);

    const int r0 = g0 + warp * 16;
    float4 a[16];
    float d[16];
#pragma unroll
    for (int i = 0; i < 16; i++) a[i] = __ldcs(&nrow[(size_t)(r0 + i) * 32 + lane]);
#pragma unroll
    for (int i = 0; i < 16; i++)
        d[i] = a[i].x * sc.x + a[i].y * sc.y + a[i].z * sc.z + a[i].w * sc.w;
#pragma unroll
    for (int off = 16; off > 0; off >>= 1) {
#pragma unroll
        for (int i = 0; i < 16; i++) d[i] += __shfl_xor_sync(0xFFFFFFFFu, d[i], off);
    }
    if (lane == 0) {
#pragma unroll
        for (int q = 0; q < 4; q++) {
            float4 m = mask4[(r0 >> 2) + q];
            float4 o;
            o.x = d[q * 4 + 0] * inv + m.x;
            o.y = d[q * 4 + 1] * inv + m.y;
            o.z = d[q * 4 + 2] * inv + m.z;
            o.w = d[q * 4 + 3] * inv + m.w;
            out4[(r0 >> 2) + q] = o;
        }
    }
}

// ---------------------------------------------------------------------------
// Kernel 3 (fused): bitonic sort of 2048 keys, 4/thread x 512 threads.
// j in {1,2} in-register, j in {4..64} shfl, j>=128 smem (10 barrier stages).
// Then LSE + policy + gather/transpose of top-128 rows.
// ---------------------------------------------------------------------------
__device__ __forceinline__ unsigned f2sortable(float v) {
    unsigned u = __float_as_uint(v);
    return (u & 0x80000000u) ? ~u : (u | 0x80000000u);
}
__device__ __forceinline__ float sortable2f(unsigned u) {
    return __uint_as_float((u & 0x80000000u) ? (u ^ 0x80000000u) : ~u);
}
__device__ __forceinline__ unsigned long long umax64(unsigned long long a, unsigned long long b) { return a > b ? a : b; }
__device__ __forceinline__ unsigned long long umin64(unsigned long long a, unsigned long long b) { return a < b ? a : b; }

__global__ void __launch_bounds__(512)
topk_gather_kernel(const float* __restrict__ node,
                   float* __restrict__ out,
                   float* __restrict__ out_policy) {
    const int b = blockIdx.x;
    const int t = threadIdx.x;  // 0..511, owns elements 4t..4t+3
    __shared__ union {
        unsigned long long keys[Gdim];  // 16 KB (sort)
        float tile[Kdim][33];           // 16.9 KB (gather)
    } u;
    __shared__ int   s_idx[Kdim];
    __shared__ float s_tv[Kdim];
    __shared__ float red[16];
    __shared__ float s_max, s_lse;

    unsigned long long k[4];
#pragma unroll
    for (int i = 0; i < 4; i++) {
        int e = 4 * t + i;
        float v = g_scores[b * Gdim + e];
        k[i] = ((unsigned long long)f2sortable(v) << 32) |
               (unsigned)(0xFFFFFFFFu - (unsigned)e);
    }

#define CMP_PAIR(lo, hi, desc)                                   \
    { unsigned long long _a = k[lo], _b = k[hi];                  \
      k[lo] = (desc) ? umax64(_a, _b) : umin64(_a, _b);           \
      k[hi] = (desc) ? umin64(_a, _b) : umax64(_a, _b); }

    // kk = 2: j=1, pair (0,1) desc, (2,3) asc
    CMP_PAIR(0, 1, true)
    CMP_PAIR(2, 3, false)

#pragma unroll
    for (int kk = 4; kk <= Gdim; kk <<= 1) {
        const int kkq = kk >> 2;
        // smem stages: j >= 128
#pragma unroll
        for (int j = kk >> 1; j >= 128; j >>= 1) {
            const int jq = j >> 2;
#pragma unroll
            for (int i = 0; i < 4; i++) u.keys[4 * t + i] = k[i];
            __syncthreads();
            bool descT = ((t & kkq) == 0);
            bool upper = ((t & jq) != 0);
            bool keepmax = (descT != upper);
            const int tp = (t ^ jq) * 4;
#pragma unroll
            for (int i = 0; i < 4; i++) {
                unsigned long long o = u.keys[tp + i];
                k[i] = keepmax ? umax64(k[i], o) : umin64(k[i], o);
            }
            __syncthreads();
        }
        // shfl stages: 4 <= j <= 64
#pragma unroll
        for (int j = (kk >> 1) < 64 ? (kk >> 1) : 64; j >= 4; j >>= 1) {
            const int jq = j >> 2;
            bool descT = ((t & kkq) == 0);
            bool upper = ((t & jq) != 0);
            bool keepmax = (descT != upper);
#pragma unroll
            for (int i = 0; i < 4; i++) {
                unsigned long long o = __shfl_xor_sync(0xFFFFFFFFu, k[i], jq);
                k[i] = keepmax ? umax64(k[i], o) : umin64(k[i], o);
            }
        }
        // in-thread j=2, j=1 (descT uniform for kk>=4)
        {
            bool descT = ((t & kkq) == 0);
            CMP_PAIR(0, 2, descT)
            CMP_PAIR(1, 3, descT)
            CMP_PAIR(0, 1, descT)
            CMP_PAIR(2, 3, descT)
        }
    }
#undef CMP_PAIR

    float v[4];
#pragma unroll
    for (int i = 0; i < 4; i++) v[i] = sortable2f((unsigned)(k[i] >> 32));

    if (t == 0) s_max = v[0];
    __syncthreads();
    const float maxv = s_max;

    // log-sum-exp over all 2048 (feeds only policy)
    float su = __expf(v[0] - maxv) + __expf(v[1] - maxv) +
               __expf(v[2] - maxv) + __expf(v[3] - maxv);
#pragma unroll
    for (int off = 16; off > 0; off >>= 1) su += __shfl_xor_sync(0xFFFFFFFFu, su, off);
    if ((t & 31) == 0) red[t >> 5] = su;
    __syncthreads();
    if (t == 0) {
        float tot = 0.f;
#pragma unroll
        for (int w = 0; w < 16; w++) tot += red[w];
        s_lse = __logf(tot);
    }
    __syncthreads();
    const float lse = s_lse;

    // top-128 lives in threads 0..31 (warp 0)
    if (t < 32) {
        float p = 0.f;
#pragma unroll
        for (int i = 0; i < 4; i++) {
            int e = 4 * t + i;
            s_idx[e] = (int)(0xFFFFFFFFu - (unsigned)(k[i] & 0xFFFFFFFFu));
            s_tv[e]  = tanh_fast(v[i]);
            p += v[i] - maxv - lse;
        }
#pragma unroll
        for (int off = 16; off > 0; off >>= 1)
            p += __shfl_xor_sync(0xFFFFFFFFu, p, off);
        if (t == 0) out_policy[b] = p * (1.0f / Kdim);
    }
    __syncthreads();

    // ---- gather + transpose: out[b,f,k] = node[b, idx[k], f] * tv[k] ----
    // 512 threads: row = t>>2 (k index), q = t&3 owns 8 float4 of the row.
    const int row = t >> 2;
    const int q   = t & 3;
    const int idx = s_idx[row];
    const float tv = s_tv[row];
    const float4* node4 = reinterpret_cast<const float4*>(node) +
                          ((size_t)b * Gdim + idx) * 32;
    float4 vv[8];
#pragma unroll
    for (int s4 = 0; s4 < 4; s4++)
#pragma unroll
        for (int ii = 0; ii < 2; ii++)
            vv[s4 * 2 + ii] = node4[s4 * 8 + q * 2 + ii];

    const int kq = t & 127;
    const int fq = t >> 7;  // 0..3
#pragma unroll
    for (int s4 = 0; s4 < 4; s4++) {
        __syncthreads();
#pragma unroll
        for (int ii = 0; ii < 2; ii++) {
            const float4 w = vv[s4 * 2 + ii];
            const int fl = (q * 2 + ii) * 4;
            u.tile[row][fl + 0] = w.x * tv;
            u.tile[row][fl + 1] = w.y * tv;
            u.tile[row][fl + 2] = w.z * tv;
            u.tile[row][fl + 3] = w.w * tv;
        }
        __syncthreads();
#pragma unroll
        for (int i = 0; i < 8; i++) {
            int fl = fq + i * 4;  // 0..31 local f
            out[((size_t)b * Fdim + s4 * 32 + fl) * Kdim + kq] = u.tile[kq][fl];
        }
    }
}

// ---------------------------------------------------------------------------
extern "C" void kernel_launch(void* const* d_in, const int* in_sizes, int n_in,
                              void* d_out, int out_size) {
    const float* node  = (const float*)d_in[0];
    const float* mask  = (const float*)d_in[1];
    const float* h_t   = (const float*)d_in[2];
    const float* W_map = (const float*)d_in[3];
    const float* b_map = (const float*)d_in[4];

    float* out = (float*)d_out;
    float* out_policy = out + (size_t)Bdim * Fdim * Kdim;

    {
        dim3 grid(2, Bdim);
        scorer_kernel<<<grid, 256>>>(h_t, W_map, b_map);
    }
    {
        dim3 grid(Gdim / 128, Bdim);
        scores_kernel<<<grid, 256>>>(node, mask);
    }
    topk_gather_kernel<<<Bdim, 512>>>(node, out, out_policy);
}